// round 15
// baseline (speedup 1.0000x reference)
#include <cuda_runtime.h>
#include <cuda_fp16.h>
#include <cstdint>
#include <cstddef>

#define NPAIRS 50000
#define NFEAT  1140
#define NEDGE  38

#define NT16   (NPAIRS / 16)            /* 3125 A row-tiles (exact)        */
#define KT16   72                       /* k16 tiles: K padded to 1152     */
#define NP16   72                       /* j 16-col pair-tiles: j pad 1152 */
#define BM     256                      /* rows per CTA (16 m16 tiles)     */
#define BN     128
#define NSTG   36                       /* stages of BK=32 (2 k16 each)    */
#define JT     9                        /* j passes of 128                 */
#define NTILES ((NPAIRS + BM - 1) / BM) /* 196                             */

#define A_STG  4096                     /* u32 per A stage: 16 tiles x 256 */
#define B_STG  2048                     /* u32 per B stage:  8 tiles x 256 */
#define SMEM_U32 (3 * A_STG + 3 * B_STG + 256)
#define SMEM_BYTES (SMEM_U32 * 4)       /* 74752 B -> dynamic smem         */

// Fragment-major fp16 scratch (device bss — no runtime allocation).
// A tile [16m x 16k] = 128 u32 ordered [lane][4 regs a0..a3].
// B tile [16k x 16j] = 128 u32 ordered [lane][4 regs b0,b1,b0',b1'].
__device__ __align__(256) uint32_t g_a[(size_t)NT16 * KT16 * 128];          // 115.2 MB
__device__ __align__(256) uint32_t g_b[(size_t)NEDGE * NP16 * KT16 * 128];  // 100.8 MB

__device__ __forceinline__ void cp16z(uint32_t sdst, const void* gsrc, bool pred) {
    int sz = pred ? 16 : 0;
    asm volatile("cp.async.cg.shared.global [%0], [%1], 16, %2;\n"
                 :: "r"(sdst), "l"(gsrc), "r"(sz));
}

__device__ __forceinline__ void mma16(float* c, uint4 a, uint32_t b0, uint32_t b1) {
    asm volatile(
        "mma.sync.aligned.m16n8k16.row.col.f32.f16.f16.f32 "
        "{%0,%1,%2,%3}, {%4,%5,%6,%7}, {%8,%9}, {%0,%1,%2,%3};"
        : "+f"(c[0]), "+f"(c[1]), "+f"(c[2]), "+f"(c[3])
        : "r"(a.x), "r"(a.y), "r"(a.z), "r"(a.w), "r"(b0), "r"(b1));
}

__device__ __forceinline__ uint32_t pack2(float lo, float hi) {
    __half l = __float2half_rn(lo), h = __float2half_rn(hi);
    return ((uint32_t)__half_as_ushort(h) << 16) | (uint32_t)__half_as_ushort(l);
}

// ---------------- prologue: convert + fragment-swizzle (every launch) ------

// A: start[n][k] -> fp16 fragments. reg r: row = g + (r&1)*8, col = 2t + (r>>1)*8.
__global__ void conv_a_k(const float* __restrict__ src) {
    __shared__ float s[16][65];
    const int nt = blockIdx.x, kb = blockIdx.y;   // kb: 0..17 (64 k each)
    const int tid = threadIdx.x;
    const int k0 = kb * 64;
    #pragma unroll
    for (int i = 0; i < 4; i++) {
        int idx = tid + i * 256;
        int row = idx >> 6, col = idx & 63;
        float v = 0.f;
        if (k0 + col < NFEAT)
            v = src[(size_t)(nt * 16 + row) * NFEAT + k0 + col];
        s[row][col] = v;
    }
    __syncthreads();
    #pragma unroll
    for (int r = 0; r < 2; r++) {
        int o = tid * 2 + r;                       // 512 u32 outputs
        int ktl = o >> 7, rem = o & 127;           // ktl 0..3
        int lane = rem >> 2, reg = rem & 3;
        int g = lane >> 2, t = lane & 3;
        int row = g + (reg & 1) * 8;
        int col = ktl * 16 + 2 * t + (reg >> 1) * 8;
        g_a[((size_t)nt * KT16 + kb * 4 + ktl) * 128 + rem] =
            pack2(s[row][col], s[row][col + 1]);
    }
}

// B: W[e][k][j] -> fp16 fragments (col-major n). reg r:
//   k = ktl*16 + 2t + (r&1)*8, j = g + (r>>1)*8; pair {W[k][j], W[k+1][j]}.
__global__ void conv_b_k(const float* __restrict__ w) {
    __shared__ float sb[64][17];
    const int kb = blockIdx.x, np = blockIdx.y, e = blockIdx.z;
    const int tid = threadIdx.x;
    const int k0 = kb * 64, j0 = np * 16;
    #pragma unroll
    for (int i = 0; i < 4; i++) {
        int idx = tid + i * 256;
        int row = idx >> 4, col = idx & 15;
        float v = 0.f;
        if (k0 + row < NFEAT && j0 + col < NFEAT)
            v = w[((size_t)e * NFEAT + k0 + row) * NFEAT + j0 + col];
        sb[row][col] = v;
    }
    __syncthreads();
    #pragma unroll
    for (int r = 0; r < 2; r++) {
        int o = tid * 2 + r;                       // 512 u32 outputs
        int ktl = o >> 7, rem = o & 127;           // ktl 0..3
        int lane = rem >> 2, reg = rem & 3;
        int g = lane >> 2, t = lane & 3;
        int krow = ktl * 16 + 2 * t + (reg & 1) * 8;
        int jcol = g + (reg >> 1) * 8;
        g_b[(((size_t)e * NP16 + np) * KT16 + kb * 4 + ktl) * 128 + rem] =
            pack2(sb[krow][jcol], sb[krow + 1][jcol]);
    }
}

// ---------------- main HMMA kernel ------------------------------------------

__global__ void __launch_bounds__(512, 1)
kway_hmma(const float* __restrict__ end_emb, float* __restrict__ out)
{
    extern __shared__ __align__(16) uint32_t smem[];
    uint32_t* Abuf = smem;                          // [3][A_STG]
    float*    osum = (float*)(smem + 3 * A_STG + 3 * B_STG);  // [BM]

    const int tid  = threadIdx.x;
    const int lane = tid & 31;
    const int wid  = tid >> 5;
    const int warp_m = wid & 7;     // 8 strips of 32 rows
    const int warp_n = wid >> 3;    // 2 strips of 64 j
    const int g = lane >> 2;
    const int t = lane & 3;

    const int n0  = blockIdx.x * BM;
    const int e   = blockIdx.y;
    const int nt0 = n0 >> 4;
    const uint32_t* __restrict__ Bg = g_b + (size_t)e * NP16 * KT16 * 128;

    const uint32_t a_sm = (uint32_t)__cvta_generic_to_shared(Abuf);
    const uint32_t b_sm = a_sm + 3 * A_STG * 4;

    float rowsum[2][2] = {{0.f, 0.f}, {0.f, 0.f}};
    for (int r = tid; r < BM; r += 512) osum[r] = 0.f;

    for (int jt = 0; jt < JT; jt++) {
        const int np0 = jt * 8;

        float acc[2][8][4];
        #pragma unroll
        for (int mt = 0; mt < 2; mt++)
            #pragma unroll
            for (int nt = 0; nt < 8; nt++)
                #pragma unroll
                for (int q = 0; q < 4; q++) acc[mt][nt][q] = 0.f;

        // ---- stage loader: A 1024 cp16 (2/thr), B 512 cp16 (1/thr) ----
        #define LOAD_STAGE(BUF, KT2)                                            \
        do {                                                                    \
            const int _k16 = (KT2) * 2;                                         \
            _Pragma("unroll")                                                   \
            for (int _i = 0; _i < 2; _i++) {                                    \
                int _c = tid + _i * 512;                                        \
                int _mt = _c >> 6, _rem = _c & 63;                              \
                int _tile = nt0 + _mt;                                          \
                bool _p = _tile < NT16;                                         \
                const uint32_t* _src =                                          \
                    g_a + ((size_t)(_p ? _tile : 0) * KT16 + _k16) * 128        \
                        + _rem * 4;                                             \
                cp16z(a_sm + ((BUF) * A_STG + _mt * 256 + _rem * 4) * 4,        \
                      _src, _p);                                                \
            }                                                                   \
            {                                                                   \
                int _np = tid >> 6, _rem = tid & 63;                            \
                const uint32_t* _src =                                          \
                    Bg + ((size_t)(np0 + _np) * KT16 + _k16) * 128 + _rem * 4;  \
                cp16z(b_sm + ((BUF) * B_STG + _np * 256 + _rem * 4) * 4,        \
                      _src, true);                                              \
            }                                                                   \
        } while (0)

        LOAD_STAGE(0, 0);
        asm volatile("cp.async.commit_group;\n" ::: "memory");
        LOAD_STAGE(1, 1);
        asm volatile("cp.async.commit_group;\n" ::: "memory");

        for (int kt = 0; kt < NSTG; kt++) {
            const int buf = kt % 3;
            asm volatile("cp.async.wait_group 1;\n" ::: "memory");
            __syncthreads();     // single barrier per stage (3-buffer ring)

            if (kt + 2 < NSTG) LOAD_STAGE((kt + 2) % 3, kt + 2);
            asm volatile("cp.async.commit_group;\n" ::: "memory");

            const uint32_t* Ab = Abuf + buf * A_STG;
            const uint32_t* Bb = Abuf + 3 * A_STG + buf * B_STG;
            #pragma unroll
            for (int ksub = 0; ksub < 2; ksub++) {
                uint4 a0 = *reinterpret_cast<const uint4*>(
                    &Ab[(warp_m * 2 + 0) * 256 + ksub * 128 + lane * 4]);
                uint4 a1 = *reinterpret_cast<const uint4*>(
                    &Ab[(warp_m * 2 + 1) * 256 + ksub * 128 + lane * 4]);
                #pragma unroll
                for (int np = 0; np < 4; np++) {
                    uint4 b = *reinterpret_cast<const uint4*>(
                        &Bb[(warp_n * 4 + np) * 256 + ksub * 128 + lane * 4]);
                    mma16(acc[0][np * 2 + 0], a0, b.x, b.y);
                    mma16(acc[0][np * 2 + 1], a0, b.z, b.w);
                    mma16(acc[1][np * 2 + 0], a1, b.x, b.y);
                    mma16(acc[1][np * 2 + 1], a1, b.z, b.w);
                }
            }
        }
        #undef LOAD_STAGE

        // ---- epilogue: fp32 dot with end_emb, accumulate per owned row ----
        const int j0 = jt * BN;
        #pragma unroll
        for (int mt = 0; mt < 2; mt++) {
            #pragma unroll
            for (int rh = 0; rh < 2; rh++) {
                const int row = n0 + warp_m * 32 + mt * 16 + rh * 8 + g;
                if (row < NPAIRS) {
                    const float* er = end_emb + (size_t)row * NFEAT;
                    float s = 0.f;
                    #pragma unroll
                    for (int nt = 0; nt < 8; nt++) {
                        const int j = j0 + warp_n * 64 + nt * 8 + 2 * t;
                        if (j < NFEAT) {
                            float2 ev = *reinterpret_cast<const float2*>(er + j);
                            s += acc[mt][nt][rh * 2]     * ev.x
                               + acc[mt][nt][rh * 2 + 1] * ev.y;
                        }
                    }
                    rowsum[mt][rh] += s;
                }
            }
        }
    }

    // Reduce across t-quad, then across the 2 warp_n strips (2 deterministic
    // shared atomics per address — commutative, bit-stable).
    #pragma unroll
    for (int mt = 0; mt < 2; mt++) {
        #pragma unroll
        for (int rh = 0; rh < 2; rh++) {
            float s = rowsum[mt][rh];
            s += __shfl_xor_sync(0xffffffffu, s, 1);
            s += __shfl_xor_sync(0xffffffffu, s, 2);
            if (t == 0) {
                const int rl = warp_m * 32 + mt * 16 + rh * 8 + g;
                atomicAdd(&osum[rl], s);
            }
        }
    }
    __syncthreads();

    for (int r = tid; r < BM; r += 512) {
        const int row = n0 + r;
        if (row < NPAIRS) out[(size_t)e * NPAIRS + row] = osum[r];
    }
}

extern "C" void kernel_launch(void* const* d_in, const int* in_sizes, int n_in,
                              void* d_out, int out_size) {
    (void)in_sizes; (void)n_in; (void)out_size;
    const float* start_emb = (const float*)d_in[0];
    const float* end_emb   = (const float*)d_in[1];
    const float* weights   = (const float*)d_in[2];
    float* out = (float*)d_out;

    cudaFuncSetAttribute(kway_hmma, cudaFuncAttributeMaxDynamicSharedMemorySize,
                         SMEM_BYTES);

    conv_a_k<<<dim3(NT16, 18), 256>>>(start_emb);
    conv_b_k<<<dim3(18, NP16, NEDGE), 256>>>(weights);

    // x = n-tile (fast), y = e (slow): a concurrent wave shares one W_e in L2
    kway_hmma<<<dim3(NTILES, NEDGE), 256 /*unused*/ == 0 ? 256 : 512,
                SMEM_BYTES>>>(end_emb, out);
}